// round 5
// baseline (speedup 1.0000x reference)
#include <cuda_runtime.h>
#include <math.h>

#define Bc 2
#define Hc 16
#define Sc 2048
#define Dc 72

static constexpr int NROWS = Bc * Hc * Sc;   // 65536

// smem layout (floats)
static constexpr int QD_STRIDE = 132;            // 64*2 dup + 4 pad
static constexpr int QD_SZ = 72 * QD_STRIDE;     // 9504
static constexpr int KT_STRIDE = 68;             // 64 + 4 pad
static constexpr int KT_SZ = 72 * KT_STRIDE;     // 4896
static constexpr int VS_SZ = 64 * 72;            // 4608
static constexpr int P_STRIDE = 65;
static constexpr int P_SZ = 64 * P_STRIDE;       // 4160
static constexpr int SMEM_FLOATS = QD_SZ + KT_SZ + VS_SZ + P_SZ;   // 23168 = 92672 B

__device__ __align__(16) float g_q[(size_t)NROWS * Dc];
__device__ __align__(16) float g_k[(size_t)NROWS * Dc];

// packed fp32x2 FMA (Blackwell FFMA2 — 2x fp32 FMA throughput)
__device__ __forceinline__ void ffma2(float2& d, const float2 a, const float2 b) {
    unsigned long long dd, aa, bb;
    dd = *reinterpret_cast<const unsigned long long*>(&d);
    aa = *reinterpret_cast<const unsigned long long*>(&a);
    bb = *reinterpret_cast<const unsigned long long*>(&b);
    asm("fma.rn.f32x2 %0, %1, %2, %0;" : "+l"(dd) : "l"(aa), "l"(bb));
    d = *reinterpret_cast<const float2*>(&dd);
}

// ---------------------------------------------------------------------------
// Zero the invalid query region (rows q < 576 for every (b,h)).
// ---------------------------------------------------------------------------
__global__ void zero_kernel(float4* __restrict__ out) {
    int idx = blockIdx.x * 256 + threadIdx.x;            // < 331776
    int bh = idx / 10368;                                // 576*18 float4 per bh
    int r  = idx % 10368;
    out[(size_t)bh * (Sc * 18) + r] = make_float4(0.f, 0.f, 0.f, 0.f);
}

// ---------------------------------------------------------------------------
// Preprocess: theta + rotary + L2 norm for q and k. One warp per (b,h,s) row.
// ---------------------------------------------------------------------------
__global__ void prep_kernel(const float* __restrict__ q, const float* __restrict__ k,
                            const float* __restrict__ pos, const float* __restrict__ pos_orig,
                            const float* __restrict__ time_, const float* __restrict__ freqs,
                            const float* __restrict__ t_freqs, const float* __restrict__ scale) {
    int warp = threadIdx.x >> 5, lane = threadIdx.x & 31;
    int row = blockIdx.x * 8 + warp;                     // 0..65535
    int s  = row & (Sc - 1);
    int bh = row >> 11;
    int h  = bh & (Hc - 1);
    int b  = bh >> 4;

    const float* qr = q + (size_t)row * Dc;
    const float* kr = k + (size_t)row * Dc;

    __shared__ float sq[8][Dc], sk[8][Dc];
    for (int e = lane; e < Dc; e += 32) { sq[warp][e] = qr[e]; sk[warp][e] = kr[e]; }
    __syncwarp();

    int ps = (b * Sc + s) * 2;
    float px  = 2.f * pos[ps]       - 1.f;
    float py  = 2.f * pos[ps + 1]   - 1.f;
    float pxo = 2.f * pos_orig[ps]     - 1.f;
    float pyo = 2.f * pos_orig[ps + 1] - 1.f;
    float tm  = time_[b * Sc + s];

    float oq[3], ok[3];
    float ssq = 0.f, ssk = 0.f;
    #pragma unroll
    for (int slot = 0; slot < 3; slot++) {
        int j = lane + slot * 32;
        if (j < Dc) {
            float xq = sq[warp][j], xk = sk[warp][j];
            if (j < 60) {
                int jj = (j < 30) ? j : j - 30;
                int seg = jj / 6, i = jj % 6;
                float coef, fr;
                if      (seg == 0) { coef = pyo; fr = freqs[96 + h * 6 + i]; }
                else if (seg == 1) { coef = py;  fr = freqs[96 + h * 6 + i]; }
                else if (seg == 2) { coef = pxo; fr = freqs[h * 6 + i]; }
                else if (seg == 3) { coef = px;  fr = freqs[h * 6 + i]; }
                else               { coef = tm;  fr = t_freqs[h * 6 + i]; }
                float th = coef * fr, c, sn;
                sincosf(th, &sn, &c);
                if (j < 30) {
                    oq[slot] = xq * c - sq[warp][j + 30] * sn;
                    ok[slot] = xk * c - sk[warp][j + 30] * sn;
                } else {
                    oq[slot] = xq * c + sq[warp][j - 30] * sn;
                    ok[slot] = xk * c + sk[warp][j - 30] * sn;
                }
            } else { oq[slot] = xq; ok[slot] = xk; }
            ssq += oq[slot] * oq[slot];
            ssk += ok[slot] * ok[slot];
        } else { oq[slot] = 0.f; ok[slot] = 0.f; }
    }
    #pragma unroll
    for (int off = 16; off; off >>= 1) {
        ssq += __shfl_xor_sync(0xffffffffu, ssq, off);
        ssk += __shfl_xor_sync(0xffffffffu, ssk, off);
    }
    float ss = sqrtf(scale[h]);
    float rq = ss * rsqrtf(ssq + 1e-6f);
    float rk = ss * rsqrtf(ssk + 1e-6f);
    #pragma unroll
    for (int slot = 0; slot < 3; slot++) {
        int j = lane + slot * 32;
        if (j < Dc) {
            g_q[(size_t)row * Dc + j] = oq[slot] * rq;
            g_k[(size_t)row * Dc + j] = ok[slot] * rk;
        }
    }
}

// ---------------------------------------------------------------------------
// Attention. Scores bounded (normalized q,k) -> exp with no running max.
// grid = (23 q-tiles of 64 rows from q=576, 32 bh), 256 threads, FFMA2 core.
// ---------------------------------------------------------------------------
__global__ void __launch_bounds__(256, 2)
attn_kernel(const float* __restrict__ v, float* __restrict__ out) {
    extern __shared__ float sm[];
    float* Qd = sm;                     // [72][132] transposed, duplicated pairs
    float* Kt = sm + QD_SZ;             // [72][68]  transposed
    float* Vs = Kt + KT_SZ;             // [64][72]  row-major
    float* P  = Vs + VS_SZ;             // [64][65]

    int t  = threadIdx.x;
    int m  = blockIdx.x;
    int bh = blockIdx.y;
    int q0 = 576 + 64 * m;
    size_t base = (size_t)bh * Sc;

    {   // load Q tile -> transposed + duplicated smem
        const float4* src = (const float4*)(g_q + (base + q0) * Dc);
        for (int i = t; i < 64 * 18; i += 256) {
            float4 qv = src[i];
            int r = i / 18, c4 = (i % 18) * 4;
            float* d0 = Qd + (c4 + 0) * QD_STRIDE + 2 * r;
            float* d1 = Qd + (c4 + 1) * QD_STRIDE + 2 * r;
            float* d2 = Qd + (c4 + 2) * QD_STRIDE + 2 * r;
            float* d3 = Qd + (c4 + 3) * QD_STRIDE + 2 * r;
            d0[0] = qv.x; d0[1] = qv.x;
            d1[0] = qv.y; d1[1] = qv.y;
            d2[0] = qv.z; d2[1] = qv.z;
            d3[0] = qv.w; d3[1] = qv.w;
        }
    }

    bool causal = (m < 8);
    int nt = causal ? (10 + m) : 17;

    float2 av[9];
    #pragma unroll
    for (int i = 0; i < 9; i++) av[i] = make_float2(0.f, 0.f);
    float l = 0.f;

    int qown = t >> 2, g = t & 3;
    int ty = t >> 4, tx = t & 15;

    const float4* Qd4 = (const float4*)Qd;
    const float4* Kt4 = (const float4*)Kt;

    for (int kt = 0; kt < nt; kt++) {
        __syncthreads();   // previous phase2 done with Vs/P
        {   // load K transposed, V row-major
            const float4* ksrc = (const float4*)(g_k + (base + (size_t)kt * 64) * Dc);
            const float4* vsrc = (const float4*)(v   + (base + (size_t)kt * 64) * Dc);
            float4* vdst = (float4*)Vs;
            for (int i = t; i < 64 * 18; i += 256) {
                float4 kv = ksrc[i];
                vdst[i] = vsrc[i];
                int r = i / 18, c4 = (i % 18) * 4;
                Kt[(c4 + 0) * KT_STRIDE + r] = kv.x;
                Kt[(c4 + 1) * KT_STRIDE + r] = kv.y;
                Kt[(c4 + 2) * KT_STRIDE + r] = kv.z;
                Kt[(c4 + 3) * KT_STRIDE + r] = kv.w;
            }
        }
        __syncthreads();

        // phase 1: 4x4 microtile QK^T via packed f32x2
        float2 acc2[8];
        #pragma unroll
        for (int i = 0; i < 8; i++) acc2[i] = make_float2(0.f, 0.f);

        #pragma unroll 8
        for (int d = 0; d < Dc; d++) {
            float4 qa = Qd4[d * (QD_STRIDE / 4) + 2 * ty];       // (q0,q0,q1,q1)
            float4 qb = Qd4[d * (QD_STRIDE / 4) + 2 * ty + 1];   // (q2,q2,q3,q3)
            float4 kk = Kt4[d * (KT_STRIDE / 4) + tx];           // (k0,k1,k2,k3)
            float2 kp0 = make_float2(kk.x, kk.y);
            float2 kp1 = make_float2(kk.z, kk.w);
            float2 q0p = make_float2(qa.x, qa.y);
            float2 q1p = make_float2(qa.z, qa.w);
            float2 q2p = make_float2(qb.x, qb.y);
            float2 q3p = make_float2(qb.z, qb.w);
            ffma2(acc2[0], q0p, kp0); ffma2(acc2[1], q0p, kp1);
            ffma2(acc2[2], q1p, kp0); ffma2(acc2[3], q1p, kp1);
            ffma2(acc2[4], q2p, kp0); ffma2(acc2[5], q2p, kp1);
            ffma2(acc2[6], q3p, kp0); ffma2(acc2[7], q3p, kp1);
        }

        bool masked = causal && (kt == nt - 1);
        #pragma unroll
        for (int i = 0; i < 4; i++) {
            #pragma unroll
            for (int jp = 0; jp < 2; jp++) {
                float sx = acc2[i * 2 + jp].x;
                float sy = acc2[i * 2 + jp].y;
                int row = ty * 4 + i, col = tx * 4 + 2 * jp;
                float px = (masked && (col     > row)) ? 0.f : __expf(sx);
                float py = (masked && (col + 1 > row)) ? 0.f : __expf(sy);
                P[row * P_STRIDE + col]     = px;
                P[row * P_STRIDE + col + 1] = py;
            }
        }
        __syncthreads();

        // phase 2: O += P @ V (packed along d), thread owns (qown, dims g*18..+17)
        const float* Prow = P + qown * P_STRIDE;
        #pragma unroll 4
        for (int kk = 0; kk < 64; kk++) {
            float p = Prow[kk];
            l += p;
            float2 pd = make_float2(p, p);
            const float2* vr = (const float2*)(Vs + kk * Dc + g * 18);
            #pragma unroll
            for (int i2 = 0; i2 < 9; i2++) ffma2(av[i2], pd, vr[i2]);
        }
    }

    // unpack accumulators
    float acc[18];
    #pragma unroll
    for (int i = 0; i < 9; i++) { acc[2 * i] = av[i].x; acc[2 * i + 1] = av[i].y; }

    if (!causal) {   // self key k == q
        int qg = q0 + qown;
        const float* kr = g_k + (base + qg) * Dc + g * 18;
        const float* qrow = g_q + (base + qg) * Dc + g * 18;
        float sp = 0.f;
        #pragma unroll
        for (int i = 0; i < 18; i++) sp += qrow[i] * kr[i];
        sp += __shfl_xor_sync(0xffffffffu, sp, 1);
        sp += __shfl_xor_sync(0xffffffffu, sp, 2);
        float p = __expf(sp);
        l += p;
        const float* vr = v + (base + qg) * Dc + g * 18;
        #pragma unroll
        for (int i = 0; i < 18; i++) acc[i] += p * vr[i];
    }

    float inv = 1.f / l;
    float* orow = out + (base + q0 + qown) * Dc + g * 18;
    #pragma unroll
    for (int i = 0; i < 18; i++) orow[i] = acc[i] * inv;
}

// ---------------------------------------------------------------------------
extern "C" void kernel_launch(void* const* d_in, const int* in_sizes, int n_in,
                              void* d_out, int out_size) {
    const float* q        = (const float*)d_in[0];
    const float* k        = (const float*)d_in[1];
    const float* v        = (const float*)d_in[2];
    const float* pos      = (const float*)d_in[3];
    const float* pos_orig = (const float*)d_in[4];
    const float* time_    = (const float*)d_in[5];
    const float* freqs    = (const float*)d_in[6];
    const float* t_freqs  = (const float*)d_in[7];
    const float* scale    = (const float*)d_in[8];
    float* out = (float*)d_out;

    cudaFuncSetAttribute(attn_kernel, cudaFuncAttributeMaxDynamicSharedMemorySize,
                         SMEM_FLOATS * sizeof(float));

    zero_kernel<<<1296, 256>>>((float4*)out);
    prep_kernel<<<Bc * Hc * Sc / 8, 256>>>(q, k, pos, pos_orig, time_, freqs, t_freqs, scale);
    attn_kernel<<<dim3(23, 32), 256, SMEM_FLOATS * sizeof(float)>>>(v, out);
}

// round 11
// speedup vs baseline: 3.6431x; 3.6431x over previous
#include <cuda_runtime.h>
#include <cstdint>
#include <math.h>

#define Bc 2
#define Hc 16
#define Sc 2048
#define Dc 72

static constexpr int NROWS = Bc * Hc * Sc;   // 65536

__device__ __align__(16) float g_q[(size_t)NROWS * Dc];
__device__ __align__(16) float g_k[(size_t)NROWS * Dc];

// ---------------------------------------------------------------------------
// helpers
// ---------------------------------------------------------------------------
__device__ __forceinline__ uint32_t f2tf(float x) {
    uint32_t r;
    asm("cvt.rna.tf32.f32 %0, %1;" : "=r"(r) : "f"(x));
    return r;
}

// D += A(16x8,row) * B(8x8,col)   tf32, fp32 accum
__device__ __forceinline__ void mma8(float& d0, float& d1, float& d2, float& d3,
                                     uint32_t a0, uint32_t a1, uint32_t a2, uint32_t a3,
                                     uint32_t b0, uint32_t b1) {
    asm volatile("mma.sync.aligned.m16n8k8.row.col.f32.tf32.tf32.f32 "
                 "{%0,%1,%2,%3}, {%4,%5,%6,%7}, {%8,%9}, {%0,%1,%2,%3};"
                 : "+f"(d0), "+f"(d1), "+f"(d2), "+f"(d3)
                 : "r"(a0), "r"(a1), "r"(a2), "r"(a3), "r"(b0), "r"(b1));
}

// exp(s) for |s| <= ~2.3, FMA-pipe only (no MUFU). rel err ~2e-6.
__device__ __forceinline__ float fast_exp(float s) {
    const float L2E = 1.4426950408889634f;
    float x = s * L2E;
    int   ni = __float2int_rn(x);
    float f  = x - (float)ni;
    float p  = 0.0013333558f;
    p = fmaf(p, f, 0.0096181290f);
    p = fmaf(p, f, 0.0555041087f);
    p = fmaf(p, f, 0.2402265069f);
    p = fmaf(p, f, 0.6931471806f);
    p = fmaf(p, f, 1.0f);
    return p * __int_as_float((ni + 127) << 23);
}

// ---------------------------------------------------------------------------
// Zero the invalid query region (rows q < 576 for every (b,h)).
// ---------------------------------------------------------------------------
__global__ void zero_kernel(float4* __restrict__ out) {
    int idx = blockIdx.x * 256 + threadIdx.x;            // < 331776
    int bh = idx / 10368;
    int r  = idx % 10368;
    out[(size_t)bh * (Sc * 18) + r] = make_float4(0.f, 0.f, 0.f, 0.f);
}

// ---------------------------------------------------------------------------
// Preprocess: theta + rotary + L2 norm for q and k. One warp per (b,h,s) row.
// ---------------------------------------------------------------------------
__global__ void prep_kernel(const float* __restrict__ q, const float* __restrict__ k,
                            const float* __restrict__ pos, const float* __restrict__ pos_orig,
                            const float* __restrict__ time_, const float* __restrict__ freqs,
                            const float* __restrict__ t_freqs, const float* __restrict__ scale) {
    int warp = threadIdx.x >> 5, lane = threadIdx.x & 31;
    int row = blockIdx.x * 8 + warp;
    int s  = row & (Sc - 1);
    int bh = row >> 11;
    int h  = bh & (Hc - 1);
    int b  = bh >> 4;

    const float* qr = q + (size_t)row * Dc;
    const float* kr = k + (size_t)row * Dc;

    __shared__ float sq[8][Dc], sk[8][Dc];
    for (int e = lane; e < Dc; e += 32) { sq[warp][e] = qr[e]; sk[warp][e] = kr[e]; }
    __syncwarp();

    int ps = (b * Sc + s) * 2;
    float px  = 2.f * pos[ps]       - 1.f;
    float py  = 2.f * pos[ps + 1]   - 1.f;
    float pxo = 2.f * pos_orig[ps]     - 1.f;
    float pyo = 2.f * pos_orig[ps + 1] - 1.f;
    float tm  = time_[b * Sc + s];

    float oq[3], ok[3];
    float ssq = 0.f, ssk = 0.f;
    #pragma unroll
    for (int slot = 0; slot < 3; slot++) {
        int j = lane + slot * 32;
        if (j < Dc) {
            float xq = sq[warp][j], xk = sk[warp][j];
            if (j < 60) {
                int jj = (j < 30) ? j : j - 30;
                int seg = jj / 6, i = jj % 6;
                float coef, fr;
                if      (seg == 0) { coef = pyo; fr = freqs[96 + h * 6 + i]; }
                else if (seg == 1) { coef = py;  fr = freqs[96 + h * 6 + i]; }
                else if (seg == 2) { coef = pxo; fr = freqs[h * 6 + i]; }
                else if (seg == 3) { coef = px;  fr = freqs[h * 6 + i]; }
                else               { coef = tm;  fr = t_freqs[h * 6 + i]; }
                float th = coef * fr, c, sn;
                sincosf(th, &sn, &c);
                if (j < 30) {
                    oq[slot] = xq * c - sq[warp][j + 30] * sn;
                    ok[slot] = xk * c - sk[warp][j + 30] * sn;
                } else {
                    oq[slot] = xq * c + sq[warp][j - 30] * sn;
                    ok[slot] = xk * c + sk[warp][j - 30] * sn;
                }
            } else { oq[slot] = xq; ok[slot] = xk; }
            ssq += oq[slot] * oq[slot];
            ssk += ok[slot] * ok[slot];
        } else { oq[slot] = 0.f; ok[slot] = 0.f; }
    }
    #pragma unroll
    for (int off = 16; off; off >>= 1) {
        ssq += __shfl_xor_sync(0xffffffffu, ssq, off);
        ssk += __shfl_xor_sync(0xffffffffu, ssk, off);
    }
    float ss = sqrtf(scale[h]);
    float rq = ss * rsqrtf(ssq + 1e-6f);
    float rk = ss * rsqrtf(ssk + 1e-6f);
    #pragma unroll
    for (int slot = 0; slot < 3; slot++) {
        int j = lane + slot * 32;
        if (j < Dc) {
            g_q[(size_t)row * Dc + j] = oq[slot] * rq;
            g_k[(size_t)row * Dc + j] = ok[slot] * rk;
        }
    }
}

// ---------------------------------------------------------------------------
// Attention with warp-level tf32 mma.sync (base PTX, valid on sm_103).
// grid = (23 q-tiles of 64 from q=576, 32 bh), 128 threads (4 warps x 16 q-rows).
// Bounded scores (normalized q,k) -> no running softmax max; poly exp on FMA pipe.
// ---------------------------------------------------------------------------
static constexpr int KVS = 76;          // padded row stride (conflict-free B frags)

__global__ void __launch_bounds__(128)
attn_kernel(const float* __restrict__ v, float* __restrict__ out) {
    __shared__ uint32_t sm[2 * 64 * KVS];           // 38912 B
    uint32_t* Ks = sm;
    uint32_t* Vs = sm + 64 * KVS;
    float*    Qs = (float*)sm;                       // staging, overlaps Ks

    int tid = threadIdx.x, wid = tid >> 5, lane = tid & 31;
    int g = lane >> 2, c = lane & 3;
    int m  = blockIdx.x;
    int bh = blockIdx.y;
    int q0 = 576 + 64 * m;
    size_t base = (size_t)bh * Sc;

    // ---- stage Q tile, build tf32 A-fragments (held in regs all kernel) ----
    {
        const float4* qsrc = (const float4*)(g_q + (base + q0) * Dc);
        float4* qdst = (float4*)Qs;
        for (int i = tid; i < 64 * 18; i += 128) qdst[i] = qsrc[i];
    }
    __syncthreads();
    uint32_t aq[9][4];
    {
        const float* qb = Qs + (wid * 16) * 72;
        #pragma unroll
        for (int kb = 0; kb < 9; kb++) {
            aq[kb][0] = f2tf(qb[g * 72       + kb * 8 + c]);
            aq[kb][1] = f2tf(qb[(g + 8) * 72 + kb * 8 + c]);
            aq[kb][2] = f2tf(qb[g * 72       + kb * 8 + 4 + c]);
            aq[kb][3] = f2tf(qb[(g + 8) * 72 + kb * 8 + 4 + c]);
        }
    }
    __syncthreads();   // done reading Qs before Ks overwrites it

    float o[9][4];
    #pragma unroll
    for (int i = 0; i < 9; i++) { o[i][0] = o[i][1] = o[i][2] = o[i][3] = 0.f; }
    float l_lo = 0.f, l_hi = 0.f;

    int nt = (m < 8) ? (10 + m) : 17;
    int qrow_lo = q0 + wid * 16 + g;
    int qrow_hi = qrow_lo + 8;

    for (int kt = 0; kt < nt; kt++) {
        // ---- load K,V tile as tf32 bit patterns ----
        {
            const float4* ksrc = (const float4*)(g_k + (base + (size_t)kt * 64) * Dc);
            const float4* vsrc = (const float4*)(v   + (base + (size_t)kt * 64) * Dc);
            for (int i = tid; i < 64 * 18; i += 128) {
                int r = i / 18, c4 = (i % 18) * 4;
                float4 kv = ksrc[i];
                float4 vv = vsrc[i];
                *(uint4*)(Ks + r * KVS + c4) =
                    make_uint4(f2tf(kv.x), f2tf(kv.y), f2tf(kv.z), f2tf(kv.w));
                *(uint4*)(Vs + r * KVS + c4) =
                    make_uint4(f2tf(vv.x), f2tf(vv.y), f2tf(vv.z), f2tf(vv.w));
            }
        }
        __syncthreads();

        bool lastmask = (m < 8) && (kt == nt - 1);
        int kb_glob = kt * 64;

        #pragma unroll
        for (int nb = 0; nb < 8; nb++) {
            // S block: 16 q-rows x 8 keys
            float d0 = 0.f, d1 = 0.f, d2 = 0.f, d3 = 0.f;
            const uint32_t* kbp = Ks + (nb * 8 + g) * KVS + c;
            #pragma unroll
            for (int kb = 0; kb < 9; kb++) {
                uint32_t b0 = kbp[kb * 8];
                uint32_t b1 = kbp[kb * 8 + 4];
                mma8(d0, d1, d2, d3, aq[kb][0], aq[kb][1], aq[kb][2], aq[kb][3], b0, b1);
            }
            // exp (+ diagonal mask on last causal tile)
            float p0 = fast_exp(d0), p1 = fast_exp(d1);
            float p2 = fast_exp(d2), p3 = fast_exp(d3);
            if (lastmask) {
                int col = kb_glob + nb * 8 + 2 * c;
                if (col     > qrow_lo) p0 = 0.f;
                if (col + 1 > qrow_lo) p1 = 0.f;
                if (col     > qrow_hi) p2 = 0.f;
                if (col + 1 > qrow_hi) p3 = 0.f;
            }
            l_lo += p0 + p1;
            l_hi += p2 + p3;

            // repack D-layout -> A-layout (P fragment) via shuffles
            int srcA = (lane & ~3) + (c >> 1);
            int srcB = srcA + 2;
            float v00 = __shfl_sync(0xffffffffu, p0, srcA);
            float v01 = __shfl_sync(0xffffffffu, p1, srcA);
            float v10 = __shfl_sync(0xffffffffu, p2, srcA);
            float v11 = __shfl_sync(0xffffffffu, p3, srcA);
            float w00 = __shfl_sync(0xffffffffu, p0, srcB);
            float w01 = __shfl_sync(0xffffffffu, p1, srcB);
            float w10 = __shfl_sync(0xffffffffu, p2, srcB);
            float w11 = __shfl_sync(0xffffffffu, p3, srcB);
            bool odd = (c & 1);
            uint32_t pa0 = f2tf(odd ? v01 : v00);
            uint32_t pa1 = f2tf(odd ? v11 : v10);
            uint32_t pa2 = f2tf(odd ? w01 : w00);
            uint32_t pa3 = f2tf(odd ? w11 : w10);

            // O += P(16x8keys) @ V(8keys x 72dims)
            const uint32_t* vbp = Vs + (nb * 8 + c) * KVS + g;
            #pragma unroll
            for (int db = 0; db < 9; db++) {
                uint32_t b0 = vbp[db * 8];
                uint32_t b1 = vbp[4 * KVS + db * 8];
                mma8(o[db][0], o[db][1], o[db][2], o[db][3], pa0, pa1, pa2, pa3, b0, b1);
            }
        }
        __syncthreads();
    }

    // reduce l across the 4 lanes sharing a row group
    l_lo += __shfl_xor_sync(0xffffffffu, l_lo, 1);
    l_lo += __shfl_xor_sync(0xffffffffu, l_lo, 2);
    l_hi += __shfl_xor_sync(0xffffffffu, l_hi, 1);
    l_hi += __shfl_xor_sync(0xffffffffu, l_hi, 2);

    if (m >= 8) {   // dense rows: add the self key k == q
        const float2* qlo = (const float2*)(g_q + (base + qrow_lo) * Dc);
        const float2* klo = (const float2*)(g_k + (base + qrow_lo) * Dc);
        const float2* qhi = (const float2*)(g_q + (base + qrow_hi) * Dc);
        const float2* khi = (const float2*)(g_k + (base + qrow_hi) * Dc);
        float sl = 0.f, sh = 0.f;
        #pragma unroll
        for (int nb = 0; nb < 9; nb++) {
            float2 a = qlo[4 * nb + c], b = klo[4 * nb + c];
            sl += a.x * b.x + a.y * b.y;
            float2 e = qhi[4 * nb + c], f = khi[4 * nb + c];
            sh += e.x * f.x + e.y * f.y;
        }
        sl += __shfl_xor_sync(0xffffffffu, sl, 1);
        sl += __shfl_xor_sync(0xffffffffu, sl, 2);
        sh += __shfl_xor_sync(0xffffffffu, sh, 1);
        sh += __shfl_xor_sync(0xffffffffu, sh, 2);
        float pl = fast_exp(sl), ph = fast_exp(sh);
        l_lo += pl; l_hi += ph;
        const float2* vlo = (const float2*)(v + (base + qrow_lo) * Dc);
        const float2* vhi = (const float2*)(v + (base + qrow_hi) * Dc);
        #pragma unroll
        for (int nb = 0; nb < 9; nb++) {
            float2 a = vlo[4 * nb + c];
            o[nb][0] += pl * a.x; o[nb][1] += pl * a.y;
            float2 b = vhi[4 * nb + c];
            o[nb][2] += ph * b.x; o[nb][3] += ph * b.y;
        }
    }

    float il = 1.f / l_lo, ih = 1.f / l_hi;
    float2* olo = (float2*)(out + (base + qrow_lo) * Dc);
    float2* ohi = (float2*)(out + (base + qrow_hi) * Dc);
    #pragma unroll
    for (int nb = 0; nb < 9; nb++) {
        olo[4 * nb + c] = make_float2(o[nb][0] * il, o[nb][1] * il);
        ohi[4 * nb + c] = make_float2(o[nb][2] * ih, o[nb][3] * ih);
    }
}

// ---------------------------------------------------------------------------
extern "C" void kernel_launch(void* const* d_in, const int* in_sizes, int n_in,
                              void* d_out, int out_size) {
    const float* q        = (const float*)d_in[0];
    const float* k        = (const float*)d_in[1];
    const float* v        = (const float*)d_in[2];
    const float* pos      = (const float*)d_in[3];
    const float* pos_orig = (const float*)d_in[4];
    const float* time_    = (const float*)d_in[5];
    const float* freqs    = (const float*)d_in[6];
    const float* t_freqs  = (const float*)d_in[7];
    const float* scale    = (const float*)d_in[8];
    float* out = (float*)d_out;

    zero_kernel<<<1296, 256>>>((float4*)out);
    prep_kernel<<<Bc * Hc * Sc / 8, 256>>>(q, k, pos, pos_orig, time_, freqs, t_freqs, scale);
    attn_kernel<<<dim3(23, 32), 128>>>(v, out);
}